// round 14
// baseline (speedup 1.0000x reference)
#include <cuda_runtime.h>
#include <cstdint>

// Shapes fixed by reference setup_inputs
static constexpr int Bb = 8, Tt = 256, Uu = 64, Dd = 512, Aa = 256, Vv = 1024;
static constexpr long long Mm = (long long)Bb * Tt * Uu;   // 131072

// ---- global scratch (static __device__ arrays; allocation-free) ----
__device__ uint16_t g_Ahi[(size_t)Mm * Aa];     // split hptr
__device__ uint16_t g_Alo[(size_t)Mm * Aa];
__device__ uint16_t g_actHi[(size_t)Mm * Dd];   // split activation (k1 -> k2)
__device__ uint16_t g_actLo[(size_t)Mm * Dd];
__device__ uint16_t g_Wbhi[(size_t)Dd * Aa];
__device__ uint16_t g_Wblo[(size_t)Dd * Aa];
__device__ uint16_t g_Wohi[(size_t)Vv * Dd];
__device__ uint16_t g_Wolo[(size_t)Vv * Dd];

__device__ __forceinline__ float hif(float x) {
    return __uint_as_float(__float_as_uint(x) & 0xFFFF0000u);
}
__device__ __forceinline__ uint32_t pack2hi(float x, float y) {
    return __byte_perm(__float_as_uint(x), __float_as_uint(y), 0x7632);
}
__device__ __forceinline__ uint32_t smem_u32(const void* p) {
    uint32_t a;
    asm("{ .reg .u64 t; cvta.to.shared.u64 t, %1; cvt.u32.u64 %0, t; }" : "=r"(a) : "l"(p));
    return a;
}
__device__ __forceinline__ void cp16(uint32_t daddr, const void* src) {
    asm volatile("cp.async.cg.shared.global [%0], [%1], 16;"
                 :: "r"(daddr), "l"(src) : "memory");
}
__device__ __forceinline__ void ldsm4(uint32_t r[4], uint32_t addr) {
    asm volatile("ldmatrix.sync.aligned.m8n8.x4.shared.b16 {%0,%1,%2,%3}, [%4];"
                 : "=r"(r[0]), "=r"(r[1]), "=r"(r[2]), "=r"(r[3]) : "r"(addr));
}

#define MMA_BF16(c, a, b)                                                        \
    asm volatile(                                                                \
        "mma.sync.aligned.m16n8k16.row.col.f32.bf16.bf16.f32 "                   \
        "{%0,%1,%2,%3}, {%4,%5,%6,%7}, {%8,%9}, {%0,%1,%2,%3};"                  \
        : "+f"((c)[0]), "+f"((c)[1]), "+f"((c)[2]), "+f"((c)[3])                 \
        : "r"((a)[0]), "r"((a)[1]), "r"((a)[2]), "r"((a)[3]),                    \
          "r"((b)[0]), "r"((b)[1]))

// Split fp32 -> (hi, lo) bf16 pair (truncation; residual exact in fp32)
__global__ void split_kernel(const float4* __restrict__ in,
                             ushort4* __restrict__ hi, ushort4* __restrict__ lo,
                             long long n4)
{
    long long i = (long long)blockIdx.x * blockDim.x + threadIdx.x;
    if (i >= n4) return;
    float4 v = in[i];
    ushort4 h, l;
    h.x = (unsigned short)(__float_as_uint(v.x) >> 16);
    h.y = (unsigned short)(__float_as_uint(v.y) >> 16);
    h.z = (unsigned short)(__float_as_uint(v.z) >> 16);
    h.w = (unsigned short)(__float_as_uint(v.w) >> 16);
    l.x = (unsigned short)(__float_as_uint(v.x - hif(v.x)) >> 16);
    l.y = (unsigned short)(__float_as_uint(v.y - hif(v.y)) >> 16);
    l.z = (unsigned short)(__float_as_uint(v.z - hif(v.z)) >> 16);
    l.w = (unsigned short)(__float_as_uint(v.w - hif(v.w)) >> 16);
    hi[i] = h;
    lo[i] = l;
}

// NT GEMM, split-bf16 x3, pre-converted operands, 2 CTAs/SM, 3-stage pipeline:
// C[m,n] = sum_k A[m,k]*B[n,k]; CTA tile 128x128, BK=32.
// 256 threads, 8 warps 4(M) x 2(N); warp tile 32x64; term-major MMA order.
// Smem: XOR-swizzled 64B rows (no padding) -> 32KB/stage, 3 stages, 2 CTAs/SM.
// Pipeline: cp.async, wait_group 1 (2-iteration prefetch distance).
// FUSE=1: C = relu(acc + src + tgt + bias), also emits split-bf16 act.
template <int K, int FUSE>
__global__ __launch_bounds__(256, 2)
void mma_gemm(const uint16_t* __restrict__ Ahi, const uint16_t* __restrict__ Alo,
              const uint16_t* __restrict__ Bhi, const uint16_t* __restrict__ Blo,
              const float* __restrict__ bias,
              const float* __restrict__ src, const float* __restrict__ tgt,
              float* __restrict__ C,
              uint16_t* __restrict__ actHi, uint16_t* __restrict__ actLo,
              int N)
{
    constexpr int BK = 32;
    constexpr int KB = K / BK;
    constexpr int STAGES = 3;
    constexpr uint32_t ARR = 128u * 64u;          // 8192 B per array (64B rows)
    constexpr uint32_t STAGE_BYTES = 4u * ARR;    // 32768 B
    // swizzle: 16B-chunk index XORed with (row & 3) -> conflict-free ldsm + STS

    extern __shared__ uint8_t sw[];
    const uint32_t sbase = smem_u32(sw);

    const int tid  = threadIdx.x;
    const int wid  = tid >> 5;
    const int lane = tid & 31;
    const int gid  = lane >> 2;
    const int tig  = lane & 3;
    const int wm   = (wid & 3) * 32;       // 4 M-warps
    const int wn   = (wid >> 2) * 64;      // 2 N-warps, 64-wide warp tile
    const long long m0 = (long long)blockIdx.y * 128;
    const int n0 = blockIdx.x * 128;

    // ldmatrix lane addressing (validated R5) + swizzle masks
    const int a_row  = ((lane >> 3) & 1) * 8 + (lane & 7);
    const int a_koff = (lane >> 4) * 16;
    const int b_row  = (lane >> 4) * 8 + (lane & 7);
    const int b_koff = ((lane >> 3) & 1) * 16;
    const uint32_t axor = (uint32_t)((a_row & 3) << 4);
    const uint32_t bxor = (uint32_t)((b_row & 3) << 4);
    const uint32_t arow_off = (uint32_t)((wm + a_row) * 64);               // Ahi array
    const uint32_t brow_off = 2u * ARR + (uint32_t)((wn + b_row) * 64);    // Bhi array

    float c[2][8][4];
#pragma unroll
    for (int i = 0; i < 2; i++)
#pragma unroll
        for (int j = 0; j < 8; j++)
#pragma unroll
            for (int t = 0; t < 4; t++) c[i][j][t] = 0.0f;

    // producer: 4 arrays x 128 rows x 4 chunks(16B) = 2048 chunks / 256 thr = 8 each
    auto load_stage = [&](int kb, int buf) {
        const uint32_t stg = sbase + (uint32_t)buf * STAGE_BYTES;
#pragma unroll
        for (int t = 0; t < 8; t++) {
            const int id  = tid + t * 256;
            const int arr = id >> 9;
            const int row = (id >> 2) & 127;
            const int q   = id & 3;
            const uint32_t so = (uint32_t)arr * ARR + (uint32_t)(row * 64)
                              + (uint32_t)((q * 16) ^ ((row & 3) << 4));
            const uint16_t* gp;
            if (arr == 0)      gp = Ahi + (m0 + row) * (long long)K;
            else if (arr == 1) gp = Alo + (m0 + row) * (long long)K;
            else if (arr == 2) gp = Bhi + (long long)(n0 + row) * K;
            else               gp = Blo + (long long)(n0 + row) * K;
            cp16(stg + so, gp + kb * BK + q * 8);
        }
        asm volatile("cp.async.commit_group;" ::: "memory");
    };

    load_stage(0, 0);
    load_stage(1, 1);

    int cbuf = 0;   // stage buffer of iteration kb
#pragma unroll 1
    for (int kb = 0; kb < KB; kb++) {
        // group #kb must be complete; group #(kb+1) may remain in flight
        asm volatile("cp.async.wait_group 1;" ::: "memory");
        __syncthreads();
        // stage (kb+2)%3's previous contents (kb-1) were consumed before the
        // barrier above. Always commit to keep group numbering consistent.
        if (kb + 2 < KB) {
            int lb = cbuf + 2; if (lb >= STAGES) lb -= STAGES;
            load_stage(kb + 2, lb);
        } else {
            asm volatile("cp.async.commit_group;" ::: "memory");   // empty group
        }

        const uint32_t stg = sbase + (uint32_t)cbuf * STAGE_BYTES;

#pragma unroll
        for (int ks = 0; ks < 2; ks++) {
            const uint32_t kB = (uint32_t)ks * 32;
            const uint32_t ac = (a_koff + kB) ^ axor;    // swizzled chunk for A
            const uint32_t bc = (b_koff + kB) ^ bxor;    // swizzled chunk for B

            uint32_t ah[2][4], al[2][4];
#pragma unroll
            for (int mi = 0; mi < 2; mi++) {
                const uint32_t a0 = stg + arow_off + mi * (16 * 64) + ac;
                ldsm4(ah[mi], a0);
                ldsm4(al[mi], a0 + ARR);
            }
            uint32_t bh[4][4];
#pragma unroll
            for (int p = 0; p < 4; p++)
                ldsm4(bh[p], stg + brow_off + p * (16 * 64) + bc);

            // term 1: al x bh  (acc reuse distance 16)
#pragma unroll
            for (int p = 0; p < 4; p++)
#pragma unroll
                for (int mi = 0; mi < 2; mi++)
#pragma unroll
                    for (int q = 0; q < 2; q++)
                        MMA_BF16(c[mi][p * 2 + q], al[mi], &bh[p][q * 2]);

            uint32_t bl[4][4];
#pragma unroll
            for (int p = 0; p < 4; p++)
                ldsm4(bl[p], stg + brow_off + p * (16 * 64) + bc + ARR);

            // term 2: ah x bl
#pragma unroll
            for (int p = 0; p < 4; p++)
#pragma unroll
                for (int mi = 0; mi < 2; mi++)
#pragma unroll
                    for (int q = 0; q < 2; q++)
                        MMA_BF16(c[mi][p * 2 + q], ah[mi], &bl[p][q * 2]);

            // term 3: ah x bh
#pragma unroll
            for (int p = 0; p < 4; p++)
#pragma unroll
                for (int mi = 0; mi < 2; mi++)
#pragma unroll
                    for (int q = 0; q < 2; q++)
                        MMA_BF16(c[mi][p * 2 + q], ah[mi], &bh[p][q * 2]);
        }

        if (++cbuf == STAGES) cbuf = 0;
    }

    // Epilogue: rows gid / gid+8 (per mi), cols wn + nj*8 + 2*tig, nj in [0,8)
#pragma unroll
    for (int mi = 0; mi < 2; mi++) {
#pragma unroll
        for (int half = 0; half < 2; half++) {
            const long long m = m0 + wm + mi * 16 + gid + half * 8;
            const float* srow = nullptr;
            const float* trow = nullptr;
            if (FUSE) {
                const int mi32 = (int)m;
                const int bi = mi32 / (Tt * Uu);
                const int r  = mi32 % (Tt * Uu);
                const int ti = r / Uu;
                const int ui = r % Uu;
                srow = src + (long long)(bi * Tt + ti) * Dd;
                trow = tgt + (long long)(bi * Uu + ui) * Dd;
            }
            float* crow = C + m * N;
#pragma unroll
            for (int nj = 0; nj < 8; nj++) {
                const int n = n0 + wn + nj * 8 + tig * 2;
                float2 bi2 = *(const float2*)(bias + n);
                float vx = c[mi][nj][half * 2 + 0] + bi2.x;
                float vy = c[mi][nj][half * 2 + 1] + bi2.y;
                if (FUSE) {
                    float2 s2 = *(const float2*)(srow + n);
                    float2 t2 = *(const float2*)(trow + n);
                    vx = fmaxf(vx + s2.x + t2.x, 0.0f);
                    vy = fmaxf(vy + s2.y + t2.y, 0.0f);
                }
                *(float2*)(crow + n) = make_float2(vx, vy);
                if (FUSE) {
                    const long long w = (m * N + n) >> 1;   // n even
                    ((uint32_t*)actHi)[w] = pack2hi(vx, vy);
                    ((uint32_t*)actLo)[w] = pack2hi(vx - hif(vx), vy - hif(vy));
                }
            }
        }
    }
}

// Pass-through of lengths, converted to the float32 output dtype.
__global__ void lengths_kernel(const int* __restrict__ sl, const int* __restrict__ tl,
                               float* __restrict__ out_sl, float* __restrict__ out_tl)
{
    int i = threadIdx.x;
    if (i < Bb) { out_sl[i] = (float)sl[i]; out_tl[i] = (float)tl[i]; }
}

extern "C" void kernel_launch(void* const* d_in, const int* in_sizes, int n_in,
                              void* d_out, int out_size)
{
    const float* src  = (const float*)d_in[0];   // (B, T, D)
    const int*   sl   = (const int*)  d_in[1];
    const float* tgt  = (const float*)d_in[2];   // (B, U, D)
    const int*   tl   = (const int*)  d_in[3];
    const float* hptr = (const float*)d_in[4];   // (M, A)
    const float* Wb   = (const float*)d_in[5];   // (D, A)
    const float* bb   = (const float*)d_in[6];
    const float* Wo   = (const float*)d_in[7];   // (V, D)
    const float* bo   = (const float*)d_in[8];

    float* out = (float*)d_out;
    const long long OFF_SL  = Mm * Vv;
    const long long OFF_TL  = OFF_SL + Bb;
    const long long OFF_ACT = OFF_TL + Bb;
    float* out_main = out;
    float* out_act  = out + OFF_ACT;

    uint16_t *pAhi, *pAlo, *pActHi, *pActLo, *pWbhi, *pWblo, *pWohi, *pWolo;
    cudaGetSymbolAddress((void**)&pAhi,   g_Ahi);
    cudaGetSymbolAddress((void**)&pAlo,   g_Alo);
    cudaGetSymbolAddress((void**)&pActHi, g_actHi);
    cudaGetSymbolAddress((void**)&pActLo, g_actLo);
    cudaGetSymbolAddress((void**)&pWbhi,  g_Wbhi);
    cudaGetSymbolAddress((void**)&pWblo,  g_Wblo);
    cudaGetSymbolAddress((void**)&pWohi,  g_Wohi);
    cudaGetSymbolAddress((void**)&pWolo,  g_Wolo);

    // pre-split inputs
    {
        long long n4 = Mm * Aa / 4;
        split_kernel<<<(unsigned)((n4 + 255) / 256), 256>>>(
            (const float4*)hptr, (ushort4*)pAhi, (ushort4*)pAlo, n4);
        n4 = (long long)Dd * Aa / 4;
        split_kernel<<<(unsigned)((n4 + 255) / 256), 256>>>(
            (const float4*)Wb, (ushort4*)pWbhi, (ushort4*)pWblo, n4);
        n4 = (long long)Vv * Dd / 4;
        split_kernel<<<(unsigned)((n4 + 255) / 256), 256>>>(
            (const float4*)Wo, (ushort4*)pWohi, (ushort4*)pWolo, n4);
    }

    const int SMEM = 3 * 32768;   // 98304 B: 3 stages, swizzled (2 CTAs/SM fit)
    cudaFuncSetAttribute((const void*)mma_gemm<Aa, 1>,
                         cudaFuncAttributeMaxDynamicSharedMemorySize, SMEM);
    cudaFuncSetAttribute((const void*)mma_gemm<Dd, 0>,
                         cudaFuncAttributeMaxDynamicSharedMemorySize, SMEM);

    dim3 blk(256);
    // Kernel 1: act = relu(src + tgt + hptr @ Wb^T + bb); also emits split act
    dim3 g1(Dd / 128, (unsigned)(Mm / 128));
    mma_gemm<Aa, 1><<<g1, blk, SMEM>>>(pAhi, pAlo, pWbhi, pWblo, bb, src, tgt,
                                       out_act, pActHi, pActLo, Dd);
    // Kernel 2: out = act @ Wo^T + bo
    dim3 g2(Vv / 128, (unsigned)(Mm / 128));
    mma_gemm<Dd, 0><<<g2, blk, SMEM>>>(pActHi, pActLo, pWohi, pWolo, bo,
                                       nullptr, nullptr, out_main, nullptr, nullptr, Vv);

    lengths_kernel<<<1, 32>>>(sl, tl, out + OFF_SL, out + OFF_TL);

    (void)in_sizes; (void)n_in; (void)out_size;
}

// round 15
// speedup vs baseline: 1.1884x; 1.1884x over previous
#include <cuda_runtime.h>
#include <cstdint>

// Shapes fixed by reference setup_inputs
static constexpr int Bb = 8, Tt = 256, Uu = 64, Dd = 512, Aa = 256, Vv = 1024;
static constexpr long long Mm = (long long)Bb * Tt * Uu;   // 131072

// ---- global scratch (static __device__ arrays; allocation-free) ----
__device__ uint16_t g_Ahi[(size_t)Mm * Aa];     // split hptr
__device__ uint16_t g_Alo[(size_t)Mm * Aa];
__device__ uint16_t g_actHi[(size_t)Mm * Dd];   // split activation (k1 -> k2)
__device__ uint16_t g_actLo[(size_t)Mm * Dd];
__device__ uint16_t g_Wbhi[(size_t)Dd * Aa];
__device__ uint16_t g_Wblo[(size_t)Dd * Aa];
__device__ uint16_t g_Wohi[(size_t)Vv * Dd];
__device__ uint16_t g_Wolo[(size_t)Vv * Dd];

__device__ __forceinline__ float hif(float x) {
    return __uint_as_float(__float_as_uint(x) & 0xFFFF0000u);
}
__device__ __forceinline__ uint32_t pack2hi(float x, float y) {
    return __byte_perm(__float_as_uint(x), __float_as_uint(y), 0x7632);
}
__device__ __forceinline__ uint32_t smem_u32(const void* p) {
    uint32_t a;
    asm("{ .reg .u64 t; cvta.to.shared.u64 t, %1; cvt.u32.u64 %0, t; }" : "=r"(a) : "l"(p));
    return a;
}
__device__ __forceinline__ void cp16(uint32_t daddr, const void* src) {
    asm volatile("cp.async.cg.shared.global [%0], [%1], 16;"
                 :: "r"(daddr), "l"(src) : "memory");
}
__device__ __forceinline__ void ldsm4(uint32_t r[4], uint32_t addr) {
    asm volatile("ldmatrix.sync.aligned.m8n8.x4.shared.b16 {%0,%1,%2,%3}, [%4];"
                 : "=r"(r[0]), "=r"(r[1]), "=r"(r[2]), "=r"(r[3]) : "r"(addr));
}

#define MMA_BF16(c, a, b)                                                        \
    asm volatile(                                                                \
        "mma.sync.aligned.m16n8k16.row.col.f32.bf16.bf16.f32 "                   \
        "{%0,%1,%2,%3}, {%4,%5,%6,%7}, {%8,%9}, {%0,%1,%2,%3};"                  \
        : "+f"((c)[0]), "+f"((c)[1]), "+f"((c)[2]), "+f"((c)[3])                 \
        : "r"((a)[0]), "r"((a)[1]), "r"((a)[2]), "r"((a)[3]),                    \
          "r"((b)[0]), "r"((b)[1]))

// Split fp32 -> (hi, lo) bf16 pair (truncation; residual exact in fp32)
__global__ void split_kernel(const float4* __restrict__ in,
                             ushort4* __restrict__ hi, ushort4* __restrict__ lo,
                             long long n4)
{
    long long i = (long long)blockIdx.x * blockDim.x + threadIdx.x;
    if (i >= n4) return;
    float4 v = in[i];
    ushort4 h, l;
    h.x = (unsigned short)(__float_as_uint(v.x) >> 16);
    h.y = (unsigned short)(__float_as_uint(v.y) >> 16);
    h.z = (unsigned short)(__float_as_uint(v.z) >> 16);
    h.w = (unsigned short)(__float_as_uint(v.w) >> 16);
    l.x = (unsigned short)(__float_as_uint(v.x - hif(v.x)) >> 16);
    l.y = (unsigned short)(__float_as_uint(v.y - hif(v.y)) >> 16);
    l.z = (unsigned short)(__float_as_uint(v.z - hif(v.z)) >> 16);
    l.w = (unsigned short)(__float_as_uint(v.w - hif(v.w)) >> 16);
    hi[i] = h;
    lo[i] = l;
}

// NT GEMM, split-bf16 x3, pre-converted operands, 2 CTAs/SM, 3-stage pipeline:
// C[m,n] = sum_k A[m,k]*B[n,k]; CTA tile 128x128, BK=32.
// 256 threads, 8 warps 4(M) x 2(N); warp tile 32x64; term-major MMA order.
// Smem: SW64-swizzled 64B rows (chunk bits[5:4] ^= row bits[2:1]) -> no padding,
// 32KB/stage, 3 stages, 2 CTAs/SM. cp.async wait_group 1 (prefetch distance 2).
// FUSE=1: C = relu(acc + src + tgt + bias), also emits split-bf16 act.
template <int K, int FUSE>
__global__ __launch_bounds__(256, 2)
void mma_gemm(const uint16_t* __restrict__ Ahi, const uint16_t* __restrict__ Alo,
              const uint16_t* __restrict__ Bhi, const uint16_t* __restrict__ Blo,
              const float* __restrict__ bias,
              const float* __restrict__ src, const float* __restrict__ tgt,
              float* __restrict__ C,
              uint16_t* __restrict__ actHi, uint16_t* __restrict__ actLo,
              int N)
{
    constexpr int BK = 32;
    constexpr int KB = K / BK;
    constexpr int STAGES = 3;
    constexpr uint32_t ARR = 128u * 64u;          // 8192 B per array (64B rows)
    constexpr uint32_t STAGE_BYTES = 4u * ARR;    // 32768 B

    extern __shared__ uint8_t sw[];
    const uint32_t sbase = smem_u32(sw);

    const int tid  = threadIdx.x;
    const int wid  = tid >> 5;
    const int lane = tid & 31;
    const int gid  = lane >> 2;
    const int tig  = lane & 3;
    const int wm   = (wid & 3) * 32;       // 4 M-warps
    const int wn   = (wid >> 2) * 64;      // 2 N-warps, 64-wide warp tile
    const long long m0 = (long long)blockIdx.y * 128;
    const int n0 = blockIdx.x * 128;

    // ldmatrix lane addressing (validated R5) + SW64 swizzle masks
    const int a_row  = ((lane >> 3) & 1) * 8 + (lane & 7);
    const int a_koff = (lane >> 4) * 16;
    const int b_row  = (lane >> 4) * 8 + (lane & 7);
    const int b_koff = ((lane >> 3) & 1) * 16;
    // SW64: chunk bits [5:4] ^= row bits [2:1]  (row-tile offsets are x16 -> safe)
    const uint32_t axor = (uint32_t)(((a_row >> 1) & 3) << 4);
    const uint32_t bxor = (uint32_t)(((b_row >> 1) & 3) << 4);
    const uint32_t arow_off = (uint32_t)((wm + a_row) * 64);               // Ahi array
    const uint32_t brow_off = 2u * ARR + (uint32_t)((wn + b_row) * 64);    // Bhi array

    float c[2][8][4];
#pragma unroll
    for (int i = 0; i < 2; i++)
#pragma unroll
        for (int j = 0; j < 8; j++)
#pragma unroll
            for (int t = 0; t < 4; t++) c[i][j][t] = 0.0f;

    // producer: 4 arrays x 128 rows x 4 chunks(16B) = 2048 chunks / 256 thr = 8 each
    auto load_stage = [&](int kb, int buf) {
        const uint32_t stg = sbase + (uint32_t)buf * STAGE_BYTES;
#pragma unroll
        for (int t = 0; t < 8; t++) {
            const int id  = tid + t * 256;
            const int arr = id >> 9;
            const int row = (id >> 2) & 127;
            const int q   = id & 3;
            const uint32_t so = (uint32_t)arr * ARR + (uint32_t)(row * 64)
                              + (uint32_t)((q * 16) ^ (((row >> 1) & 3) << 4));
            const uint16_t* gp;
            if (arr == 0)      gp = Ahi + (m0 + row) * (long long)K;
            else if (arr == 1) gp = Alo + (m0 + row) * (long long)K;
            else if (arr == 2) gp = Bhi + (long long)(n0 + row) * K;
            else               gp = Blo + (long long)(n0 + row) * K;
            cp16(stg + so, gp + kb * BK + q * 8);
        }
        asm volatile("cp.async.commit_group;" ::: "memory");
    };

    load_stage(0, 0);
    load_stage(1, 1);

    int cbuf = 0;   // stage buffer of iteration kb
#pragma unroll 1
    for (int kb = 0; kb < KB; kb++) {
        // group #kb must be complete; group #(kb+1) may remain in flight
        asm volatile("cp.async.wait_group 1;" ::: "memory");
        __syncthreads();
        // stage (kb+2)%3's previous contents (kb-1) were consumed before the
        // barrier above. Always commit to keep group numbering consistent.
        if (kb + 2 < KB) {
            int lb = cbuf + 2; if (lb >= STAGES) lb -= STAGES;
            load_stage(kb + 2, lb);
        } else {
            asm volatile("cp.async.commit_group;" ::: "memory");   // empty group
        }

        const uint32_t stg = sbase + (uint32_t)cbuf * STAGE_BYTES;

#pragma unroll
        for (int ks = 0; ks < 2; ks++) {
            const uint32_t kB = (uint32_t)ks * 32;
            const uint32_t ac = (a_koff + kB) ^ axor;    // swizzled chunk for A
            const uint32_t bc = (b_koff + kB) ^ bxor;    // swizzled chunk for B

            uint32_t ah[2][4], al[2][4];
#pragma unroll
            for (int mi = 0; mi < 2; mi++) {
                const uint32_t a0 = stg + arow_off + mi * (16 * 64) + ac;
                ldsm4(ah[mi], a0);
                ldsm4(al[mi], a0 + ARR);
            }
            uint32_t bh[4][4];
#pragma unroll
            for (int p = 0; p < 4; p++)
                ldsm4(bh[p], stg + brow_off + p * (16 * 64) + bc);

            // term 1: al x bh  (acc reuse distance 16)
#pragma unroll
            for (int p = 0; p < 4; p++)
#pragma unroll
                for (int mi = 0; mi < 2; mi++)
#pragma unroll
                    for (int q = 0; q < 2; q++)
                        MMA_BF16(c[mi][p * 2 + q], al[mi], &bh[p][q * 2]);

            uint32_t bl[4][4];
#pragma unroll
            for (int p = 0; p < 4; p++)
                ldsm4(bl[p], stg + brow_off + p * (16 * 64) + bc + ARR);

            // term 2: ah x bl
#pragma unroll
            for (int p = 0; p < 4; p++)
#pragma unroll
                for (int mi = 0; mi < 2; mi++)
#pragma unroll
                    for (int q = 0; q < 2; q++)
                        MMA_BF16(c[mi][p * 2 + q], ah[mi], &bl[p][q * 2]);

            // term 3: ah x bh
#pragma unroll
            for (int p = 0; p < 4; p++)
#pragma unroll
                for (int mi = 0; mi < 2; mi++)
#pragma unroll
                    for (int q = 0; q < 2; q++)
                        MMA_BF16(c[mi][p * 2 + q], ah[mi], &bh[p][q * 2]);
        }

        if (++cbuf == STAGES) cbuf = 0;
    }

    // Epilogue: rows gid / gid+8 (per mi), cols wn + nj*8 + 2*tig, nj in [0,8)
#pragma unroll
    for (int mi = 0; mi < 2; mi++) {
#pragma unroll
        for (int half = 0; half < 2; half++) {
            const long long m = m0 + wm + mi * 16 + gid + half * 8;
            const float* srow = nullptr;
            const float* trow = nullptr;
            if (FUSE) {
                const int mi32 = (int)m;
                const int bi = mi32 / (Tt * Uu);
                const int r  = mi32 % (Tt * Uu);
                const int ti = r / Uu;
                const int ui = r % Uu;
                srow = src + (long long)(bi * Tt + ti) * Dd;
                trow = tgt + (long long)(bi * Uu + ui) * Dd;
            }
            float* crow = C + m * N;
#pragma unroll
            for (int nj = 0; nj < 8; nj++) {
                const int n = n0 + wn + nj * 8 + tig * 2;
                float2 bi2 = *(const float2*)(bias + n);
                float vx = c[mi][nj][half * 2 + 0] + bi2.x;
                float vy = c[mi][nj][half * 2 + 1] + bi2.y;
                if (FUSE) {
                    float2 s2 = *(const float2*)(srow + n);
                    float2 t2 = *(const float2*)(trow + n);
                    vx = fmaxf(vx + s2.x + t2.x, 0.0f);
                    vy = fmaxf(vy + s2.y + t2.y, 0.0f);
                }
                *(float2*)(crow + n) = make_float2(vx, vy);
                if (FUSE) {
                    const long long w = (m * N + n) >> 1;   // n even
                    ((uint32_t*)actHi)[w] = pack2hi(vx, vy);
                    ((uint32_t*)actLo)[w] = pack2hi(vx - hif(vx), vy - hif(vy));
                }
            }
        }
    }
}

// Pass-through of lengths, converted to the float32 output dtype.
__global__ void lengths_kernel(const int* __restrict__ sl, const int* __restrict__ tl,
                               float* __restrict__ out_sl, float* __restrict__ out_tl)
{
    int i = threadIdx.x;
    if (i < Bb) { out_sl[i] = (float)sl[i]; out_tl[i] = (float)tl[i]; }
}

extern "C" void kernel_launch(void* const* d_in, const int* in_sizes, int n_in,
                              void* d_out, int out_size)
{
    const float* src  = (const float*)d_in[0];   // (B, T, D)
    const int*   sl   = (const int*)  d_in[1];
    const float* tgt  = (const float*)d_in[2];   // (B, U, D)
    const int*   tl   = (const int*)  d_in[3];
    const float* hptr = (const float*)d_in[4];   // (M, A)
    const float* Wb   = (const float*)d_in[5];   // (D, A)
    const float* bb   = (const float*)d_in[6];
    const float* Wo   = (const float*)d_in[7];   // (V, D)
    const float* bo   = (const float*)d_in[8];

    float* out = (float*)d_out;
    const long long OFF_SL  = Mm * Vv;
    const long long OFF_TL  = OFF_SL + Bb;
    const long long OFF_ACT = OFF_TL + Bb;
    float* out_main = out;
    float* out_act  = out + OFF_ACT;

    uint16_t *pAhi, *pAlo, *pActHi, *pActLo, *pWbhi, *pWblo, *pWohi, *pWolo;
    cudaGetSymbolAddress((void**)&pAhi,   g_Ahi);
    cudaGetSymbolAddress((void**)&pAlo,   g_Alo);
    cudaGetSymbolAddress((void**)&pActHi, g_actHi);
    cudaGetSymbolAddress((void**)&pActLo, g_actLo);
    cudaGetSymbolAddress((void**)&pWbhi,  g_Wbhi);
    cudaGetSymbolAddress((void**)&pWblo,  g_Wblo);
    cudaGetSymbolAddress((void**)&pWohi,  g_Wohi);
    cudaGetSymbolAddress((void**)&pWolo,  g_Wolo);

    // pre-split inputs
    {
        long long n4 = Mm * Aa / 4;
        split_kernel<<<(unsigned)((n4 + 255) / 256), 256>>>(
            (const float4*)hptr, (ushort4*)pAhi, (ushort4*)pAlo, n4);
        n4 = (long long)Dd * Aa / 4;
        split_kernel<<<(unsigned)((n4 + 255) / 256), 256>>>(
            (const float4*)Wb, (ushort4*)pWbhi, (ushort4*)pWblo, n4);
        n4 = (long long)Vv * Dd / 4;
        split_kernel<<<(unsigned)((n4 + 255) / 256), 256>>>(
            (const float4*)Wo, (ushort4*)pWohi, (ushort4*)pWolo, n4);
    }

    const int SMEM = 3 * 32768;   // 98304 B: 3 stages, SW64 swizzle (2 CTAs/SM fit)
    cudaFuncSetAttribute((const void*)mma_gemm<Aa, 1>,
                         cudaFuncAttributeMaxDynamicSharedMemorySize, SMEM);
    cudaFuncSetAttribute((const void*)mma_gemm<Dd, 0>,
                         cudaFuncAttributeMaxDynamicSharedMemorySize, SMEM);

    dim3 blk(256);
    // Kernel 1: act = relu(src + tgt + hptr @ Wb^T + bb); also emits split act
    dim3 g1(Dd / 128, (unsigned)(Mm / 128));
    mma_gemm<Aa, 1><<<g1, blk, SMEM>>>(pAhi, pAlo, pWbhi, pWblo, bb, src, tgt,
                                       out_act, pActHi, pActLo, Dd);
    // Kernel 2: out = act @ Wo^T + bo
    dim3 g2(Vv / 128, (unsigned)(Mm / 128));
    mma_gemm<Dd, 0><<<g2, blk, SMEM>>>(pActHi, pActLo, pWohi, pWolo, bo,
                                       nullptr, nullptr, out_main, nullptr, nullptr, Vv);

    lengths_kernel<<<1, 32>>>(sl, tl, out + OFF_SL, out + OFF_TL);

    (void)in_sizes; (void)n_in; (void)out_size;
}

// round 16
// speedup vs baseline: 1.6092x; 1.3541x over previous
#include <cuda_runtime.h>
#include <cstdint>

// Shapes fixed by reference setup_inputs
static constexpr int Bb = 8, Tt = 256, Uu = 64, Dd = 512, Aa = 256, Vv = 1024;
static constexpr long long Mm = (long long)Bb * Tt * Uu;   // 131072

// ---- global scratch (static __device__ arrays; allocation-free) ----
__device__ uint16_t g_Ahi[(size_t)Mm * Aa];     // split hptr
__device__ uint16_t g_Alo[(size_t)Mm * Aa];
__device__ uint16_t g_actHi[(size_t)Mm * Dd];   // split activation (k1 -> k2)
__device__ uint16_t g_actLo[(size_t)Mm * Dd];
__device__ uint16_t g_Wbhi[(size_t)Dd * Aa];
__device__ uint16_t g_Wblo[(size_t)Dd * Aa];
__device__ uint16_t g_Wohi[(size_t)Vv * Dd];
__device__ uint16_t g_Wolo[(size_t)Vv * Dd];

__device__ __forceinline__ float hif(float x) {
    return __uint_as_float(__float_as_uint(x) & 0xFFFF0000u);
}
__device__ __forceinline__ uint32_t pack2hi(float x, float y) {
    return __byte_perm(__float_as_uint(x), __float_as_uint(y), 0x7632);
}
__device__ __forceinline__ uint32_t smem_u32(const void* p) {
    uint32_t a;
    asm("{ .reg .u64 t; cvta.to.shared.u64 t, %1; cvt.u32.u64 %0, t; }" : "=r"(a) : "l"(p));
    return a;
}
__device__ __forceinline__ void cp16(uint32_t daddr, const void* src) {
    asm volatile("cp.async.cg.shared.global [%0], [%1], 16;"
                 :: "r"(daddr), "l"(src) : "memory");
}
__device__ __forceinline__ void ldsm4(uint32_t r[4], uint32_t addr) {
    asm volatile("ldmatrix.sync.aligned.m8n8.x4.shared.b16 {%0,%1,%2,%3}, [%4];"
                 : "=r"(r[0]), "=r"(r[1]), "=r"(r[2]), "=r"(r[3]) : "r"(addr));
}
// streaming (evict-first) store for write-once outputs
__device__ __forceinline__ void stcs2(float* p, float x, float y) {
    asm volatile("st.global.cs.v2.f32 [%0], {%1,%2};" :: "l"(p), "f"(x), "f"(y) : "memory");
}

#define MMA_BF16(c, a, b)                                                        \
    asm volatile(                                                                \
        "mma.sync.aligned.m16n8k16.row.col.f32.bf16.bf16.f32 "                   \
        "{%0,%1,%2,%3}, {%4,%5,%6,%7}, {%8,%9}, {%0,%1,%2,%3};"                  \
        : "+f"((c)[0]), "+f"((c)[1]), "+f"((c)[2]), "+f"((c)[3])                 \
        : "r"((a)[0]), "r"((a)[1]), "r"((a)[2]), "r"((a)[3]),                    \
          "r"((b)[0]), "r"((b)[1]))

// Split fp32 -> (hi, lo) bf16 pair (truncation; residual exact in fp32)
__global__ void split_kernel(const float4* __restrict__ in,
                             ushort4* __restrict__ hi, ushort4* __restrict__ lo,
                             long long n4)
{
    long long i = (long long)blockIdx.x * blockDim.x + threadIdx.x;
    if (i >= n4) return;
    float4 v = in[i];
    ushort4 h, l;
    h.x = (unsigned short)(__float_as_uint(v.x) >> 16);
    h.y = (unsigned short)(__float_as_uint(v.y) >> 16);
    h.z = (unsigned short)(__float_as_uint(v.z) >> 16);
    h.w = (unsigned short)(__float_as_uint(v.w) >> 16);
    l.x = (unsigned short)(__float_as_uint(v.x - hif(v.x)) >> 16);
    l.y = (unsigned short)(__float_as_uint(v.y - hif(v.y)) >> 16);
    l.z = (unsigned short)(__float_as_uint(v.z - hif(v.z)) >> 16);
    l.w = (unsigned short)(__float_as_uint(v.w - hif(v.w)) >> 16);
    hi[i] = h;
    lo[i] = l;
}

// NT GEMM, split-bf16 x3, pre-converted operands, 2 CTAs/SM (R11 config, best):
// C[m,n] = sum_k A[m,k]*B[n,k]; CTA tile 128x128, BK=32, 2-stage cp.async.
// 256 threads, 8 warps 4(M) x 2(N); warp tile 32x64; term-major MMA order
// (accumulator reuse distance 16). Write-once outputs use streaming stores.
// FUSE=1: C = relu(acc + src + tgt + bias), also emits split-bf16 act.
template <int K, int FUSE>
__global__ __launch_bounds__(256, 2)
void mma_gemm(const uint16_t* __restrict__ Ahi, const uint16_t* __restrict__ Alo,
              const uint16_t* __restrict__ Bhi, const uint16_t* __restrict__ Blo,
              const float* __restrict__ bias,
              const float* __restrict__ src, const float* __restrict__ tgt,
              float* __restrict__ C,
              uint16_t* __restrict__ actHi, uint16_t* __restrict__ actLo,
              int N)
{
    constexpr int BK = 32;
    constexpr int KB = K / BK;
    constexpr int RS = 80;                       // row stride bytes (64B data + 16 pad)
    constexpr uint32_t ARR = 128u * RS;          // 10240 B per array
    constexpr uint32_t STAGE_BYTES = 4u * ARR;   // Ahi, Alo, Bhi, Blo = 40960 B

    extern __shared__ uint8_t sw[];
    const uint32_t sbase = smem_u32(sw);

    const int tid  = threadIdx.x;
    const int wid  = tid >> 5;
    const int lane = tid & 31;
    const int gid  = lane >> 2;
    const int tig  = lane & 3;
    const int wm   = (wid & 3) * 32;       // 4 M-warps
    const int wn   = (wid >> 2) * 64;      // 2 N-warps, 64-wide warp tile
    const long long m0 = (long long)blockIdx.y * 128;
    const int n0 = blockIdx.x * 128;

    // ldmatrix lane addressing (validated R5)
    const int a_row  = ((lane >> 3) & 1) * 8 + (lane & 7);
    const int a_koff = (lane >> 4) * 16;
    const int b_row  = (lane >> 4) * 8 + (lane & 7);
    const int b_koff = ((lane >> 3) & 1) * 16;
    const uint32_t aoff = (uint32_t)((wm + a_row) * RS + a_koff);             // Ahi array
    const uint32_t boff = 2u * ARR + (uint32_t)((wn + b_row) * RS + b_koff);  // Bhi array

    float c[2][8][4];
#pragma unroll
    for (int i = 0; i < 2; i++)
#pragma unroll
        for (int j = 0; j < 8; j++)
#pragma unroll
            for (int t = 0; t < 4; t++) c[i][j][t] = 0.0f;

    // producer: 4 arrays x 128 rows x 4 chunks(16B) = 2048 chunks / 256 thr = 8 each
    auto load_stage = [&](int kb, int buf) {
        const uint32_t stg = sbase + (uint32_t)buf * STAGE_BYTES;
#pragma unroll
        for (int t = 0; t < 8; t++) {
            const int id  = tid + t * 256;
            const int arr = id >> 9;
            const int row = (id >> 2) & 127;
            const int q   = id & 3;
            const uint32_t so = (uint32_t)arr * ARR + (uint32_t)(row * RS + q * 16);
            const uint16_t* gp;
            if (arr == 0)      gp = Ahi + (m0 + row) * (long long)K;
            else if (arr == 1) gp = Alo + (m0 + row) * (long long)K;
            else if (arr == 2) gp = Bhi + (long long)(n0 + row) * K;
            else               gp = Blo + (long long)(n0 + row) * K;
            cp16(stg + so, gp + kb * BK + q * 8);
        }
        asm volatile("cp.async.commit_group;" ::: "memory");
    };

    load_stage(0, 0);

#pragma unroll 1
    for (int kb = 0; kb < KB; kb++) {
        asm volatile("cp.async.wait_group 0;" ::: "memory");
        __syncthreads();
        // buffer (kb+1)&1's previous contents (kb-1) were consumed before the
        // barrier above; safe to overwrite now.
        if (kb + 1 < KB) load_stage(kb + 1, (kb + 1) & 1);

        const uint32_t stg = sbase + (uint32_t)(kb & 1) * STAGE_BYTES;

#pragma unroll
        for (int ks = 0; ks < 2; ks++) {
            const uint32_t kB = (uint32_t)ks * 32;

            // A fragments (hi + lo)
            uint32_t ah[2][4], al[2][4];
#pragma unroll
            for (int mi = 0; mi < 2; mi++) {
                const uint32_t a0 = stg + aoff + mi * (16 * RS) + kB;
                ldsm4(ah[mi], a0);
                ldsm4(al[mi], a0 + ARR);
            }
            // All B-hi fragments for the 64-wide warp tile
            uint32_t bh[4][4];
#pragma unroll
            for (int p = 0; p < 4; p++)
                ldsm4(bh[p], stg + boff + p * (16 * RS) + kB);

            // term 1: al x bh  (16 MMAs, acc reuse distance 16)
#pragma unroll
            for (int p = 0; p < 4; p++)
#pragma unroll
                for (int mi = 0; mi < 2; mi++)
#pragma unroll
                    for (int q = 0; q < 2; q++)
                        MMA_BF16(c[mi][p * 2 + q], al[mi], &bh[p][q * 2]);

            // B-lo fragments (latency hidden under term 1)
            uint32_t bl[4][4];
#pragma unroll
            for (int p = 0; p < 4; p++)
                ldsm4(bl[p], stg + boff + p * (16 * RS) + kB + ARR);

            // term 2: ah x bl
#pragma unroll
            for (int p = 0; p < 4; p++)
#pragma unroll
                for (int mi = 0; mi < 2; mi++)
#pragma unroll
                    for (int q = 0; q < 2; q++)
                        MMA_BF16(c[mi][p * 2 + q], ah[mi], &bl[p][q * 2]);

            // term 3: ah x bh
#pragma unroll
            for (int p = 0; p < 4; p++)
#pragma unroll
                for (int mi = 0; mi < 2; mi++)
#pragma unroll
                    for (int q = 0; q < 2; q++)
                        MMA_BF16(c[mi][p * 2 + q], ah[mi], &bh[p][q * 2]);
        }
    }

    // Epilogue: rows gid / gid+8 (per mi), cols wn + nj*8 + 2*tig, nj in [0,8)
    // C is write-once -> streaming store (preserve L2 for operand reads).
#pragma unroll
    for (int mi = 0; mi < 2; mi++) {
#pragma unroll
        for (int half = 0; half < 2; half++) {
            const long long m = m0 + wm + mi * 16 + gid + half * 8;
            const float* srow = nullptr;
            const float* trow = nullptr;
            if (FUSE) {
                const int mi32 = (int)m;
                const int bi = mi32 / (Tt * Uu);
                const int r  = mi32 % (Tt * Uu);
                const int ti = r / Uu;
                const int ui = r % Uu;
                srow = src + (long long)(bi * Tt + ti) * Dd;
                trow = tgt + (long long)(bi * Uu + ui) * Dd;
            }
            float* crow = C + m * N;
#pragma unroll
            for (int nj = 0; nj < 8; nj++) {
                const int n = n0 + wn + nj * 8 + tig * 2;
                float2 bi2 = *(const float2*)(bias + n);
                float vx = c[mi][nj][half * 2 + 0] + bi2.x;
                float vy = c[mi][nj][half * 2 + 1] + bi2.y;
                if (FUSE) {
                    float2 s2 = *(const float2*)(srow + n);
                    float2 t2 = *(const float2*)(trow + n);
                    vx = fmaxf(vx + s2.x + t2.x, 0.0f);
                    vy = fmaxf(vy + s2.y + t2.y, 0.0f);
                }
                stcs2(crow + n, vx, vy);
                if (FUSE) {
                    const long long w = (m * N + n) >> 1;   // n even
                    ((uint32_t*)actHi)[w] = pack2hi(vx, vy);
                    ((uint32_t*)actLo)[w] = pack2hi(vx - hif(vx), vy - hif(vy));
                }
            }
        }
    }
}

// Pass-through of lengths, converted to the float32 output dtype.
__global__ void lengths_kernel(const int* __restrict__ sl, const int* __restrict__ tl,
                               float* __restrict__ out_sl, float* __restrict__ out_tl)
{
    int i = threadIdx.x;
    if (i < Bb) { out_sl[i] = (float)sl[i]; out_tl[i] = (float)tl[i]; }
}

extern "C" void kernel_launch(void* const* d_in, const int* in_sizes, int n_in,
                              void* d_out, int out_size)
{
    const float* src  = (const float*)d_in[0];   // (B, T, D)
    const int*   sl   = (const int*)  d_in[1];
    const float* tgt  = (const float*)d_in[2];   // (B, U, D)
    const int*   tl   = (const int*)  d_in[3];
    const float* hptr = (const float*)d_in[4];   // (M, A)
    const float* Wb   = (const float*)d_in[5];   // (D, A)
    const float* bb   = (const float*)d_in[6];
    const float* Wo   = (const float*)d_in[7];   // (V, D)
    const float* bo   = (const float*)d_in[8];

    float* out = (float*)d_out;
    const long long OFF_SL  = Mm * Vv;
    const long long OFF_TL  = OFF_SL + Bb;
    const long long OFF_ACT = OFF_TL + Bb;
    float* out_main = out;
    float* out_act  = out + OFF_ACT;

    uint16_t *pAhi, *pAlo, *pActHi, *pActLo, *pWbhi, *pWblo, *pWohi, *pWolo;
    cudaGetSymbolAddress((void**)&pAhi,   g_Ahi);
    cudaGetSymbolAddress((void**)&pAlo,   g_Alo);
    cudaGetSymbolAddress((void**)&pActHi, g_actHi);
    cudaGetSymbolAddress((void**)&pActLo, g_actLo);
    cudaGetSymbolAddress((void**)&pWbhi,  g_Wbhi);
    cudaGetSymbolAddress((void**)&pWblo,  g_Wblo);
    cudaGetSymbolAddress((void**)&pWohi,  g_Wohi);
    cudaGetSymbolAddress((void**)&pWolo,  g_Wolo);

    // pre-split inputs
    {
        long long n4 = Mm * Aa / 4;
        split_kernel<<<(unsigned)((n4 + 255) / 256), 256>>>(
            (const float4*)hptr, (ushort4*)pAhi, (ushort4*)pAlo, n4);
        n4 = (long long)Dd * Aa / 4;
        split_kernel<<<(unsigned)((n4 + 255) / 256), 256>>>(
            (const float4*)Wb, (ushort4*)pWbhi, (ushort4*)pWblo, n4);
        n4 = (long long)Vv * Dd / 4;
        split_kernel<<<(unsigned)((n4 + 255) / 256), 256>>>(
            (const float4*)Wo, (ushort4*)pWohi, (ushort4*)pWolo, n4);
    }

    const int SMEM = 2 * 40960;   // 81920 B: 2 stages x 4 arrays (2 CTAs/SM)
    cudaFuncSetAttribute((const void*)mma_gemm<Aa, 1>,
                         cudaFuncAttributeMaxDynamicSharedMemorySize, SMEM);
    cudaFuncSetAttribute((const void*)mma_gemm<Dd, 0>,
                         cudaFuncAttributeMaxDynamicSharedMemorySize, SMEM);

    dim3 blk(256);
    // Kernel 1: act = relu(src + tgt + hptr @ Wb^T + bb); also emits split act
    dim3 g1(Dd / 128, (unsigned)(Mm / 128));
    mma_gemm<Aa, 1><<<g1, blk, SMEM>>>(pAhi, pAlo, pWbhi, pWblo, bb, src, tgt,
                                       out_act, pActHi, pActLo, Dd);
    // Kernel 2: out = act @ Wo^T + bo
    dim3 g2(Vv / 128, (unsigned)(Mm / 128));
    mma_gemm<Dd, 0><<<g2, blk, SMEM>>>(pActHi, pActLo, pWohi, pWolo, bo,
                                       nullptr, nullptr, out_main, nullptr, nullptr, Vv);

    lengths_kernel<<<1, 32>>>(sl, tl, out + OFF_SL, out + OFF_TL);

    (void)in_sizes; (void)n_in; (void)out_size;
}

// round 17
// speedup vs baseline: 1.8734x; 1.1642x over previous
#include <cuda_runtime.h>
#include <cstdint>

// Shapes fixed by reference setup_inputs
static constexpr int Bb = 8, Tt = 256, Uu = 64, Dd = 512, Aa = 256, Vv = 1024;
static constexpr long long Mm = (long long)Bb * Tt * Uu;   // 131072

// ---- global scratch (static __device__ arrays; allocation-free) ----
__device__ uint16_t g_Ahi[(size_t)Mm * Aa];     // split hptr
__device__ uint16_t g_Alo[(size_t)Mm * Aa];
__device__ uint16_t g_actHi[(size_t)Mm * Dd];   // split activation (k1 -> k2)
__device__ uint16_t g_actLo[(size_t)Mm * Dd];
__device__ uint16_t g_Wbhi[(size_t)Dd * Aa];
__device__ uint16_t g_Wblo[(size_t)Dd * Aa];
__device__ uint16_t g_Wohi[(size_t)Vv * Dd];
__device__ uint16_t g_Wolo[(size_t)Vv * Dd];

__device__ __forceinline__ float hif(float x) {
    return __uint_as_float(__float_as_uint(x) & 0xFFFF0000u);
}
__device__ __forceinline__ uint32_t pack2hi(float x, float y) {
    return __byte_perm(__float_as_uint(x), __float_as_uint(y), 0x7632);
}
__device__ __forceinline__ uint32_t smem_u32(const void* p) {
    uint32_t a;
    asm("{ .reg .u64 t; cvta.to.shared.u64 t, %1; cvt.u32.u64 %0, t; }" : "=r"(a) : "l"(p));
    return a;
}
__device__ __forceinline__ void cp16(uint32_t daddr, const void* src) {
    asm volatile("cp.async.cg.shared.global [%0], [%1], 16;"
                 :: "r"(daddr), "l"(src) : "memory");
}
__device__ __forceinline__ void ldsm4(uint32_t r[4], uint32_t addr) {
    asm volatile("ldmatrix.sync.aligned.m8n8.x4.shared.b16 {%0,%1,%2,%3}, [%4];"
                 : "=r"(r[0]), "=r"(r[1]), "=r"(r[2]), "=r"(r[3]) : "r"(addr));
}
// streaming (evict-first) store for write-once outputs
__device__ __forceinline__ void stcs2(float* p, float x, float y) {
    asm volatile("st.global.cs.v2.f32 [%0], {%1,%2};" :: "l"(p), "f"(x), "f"(y) : "memory");
}

#define MMA_BF16(c, a, b)                                                        \
    asm volatile(                                                                \
        "mma.sync.aligned.m16n8k16.row.col.f32.bf16.bf16.f32 "                   \
        "{%0,%1,%2,%3}, {%4,%5,%6,%7}, {%8,%9}, {%0,%1,%2,%3};"                  \
        : "+f"((c)[0]), "+f"((c)[1]), "+f"((c)[2]), "+f"((c)[3])                 \
        : "r"((a)[0]), "r"((a)[1]), "r"((a)[2]), "r"((a)[3]),                    \
          "r"((b)[0]), "r"((b)[1]))

// Merged split: fp32 -> (hi, lo) bf16 pairs for hptr, Wb, Wo in ONE launch.
__global__ void split_all_kernel(const float4* __restrict__ inA, ushort4* hiA, ushort4* loA, long long nA,
                                 const float4* __restrict__ inB, ushort4* hiB, ushort4* loB, long long nB,
                                 const float4* __restrict__ inC, ushort4* hiC, ushort4* loC, long long nC)
{
    long long i = (long long)blockIdx.x * blockDim.x + threadIdx.x;
    const float4* in; ushort4* hi; ushort4* lo;
    if (i < nA)            { in = inA + i;            hi = hiA + i;            lo = loA + i; }
    else if (i < nA + nB)  { i -= nA; in = inB + i;   hi = hiB + i;            lo = loB + i; }
    else if (i < nA + nB + nC) { i -= nA + nB; in = inC + i; hi = hiC + i;     lo = loC + i; }
    else return;
    float4 v = *in;
    ushort4 h, l;
    h.x = (unsigned short)(__float_as_uint(v.x) >> 16);
    h.y = (unsigned short)(__float_as_uint(v.y) >> 16);
    h.z = (unsigned short)(__float_as_uint(v.z) >> 16);
    h.w = (unsigned short)(__float_as_uint(v.w) >> 16);
    l.x = (unsigned short)(__float_as_uint(v.x - hif(v.x)) >> 16);
    l.y = (unsigned short)(__float_as_uint(v.y - hif(v.y)) >> 16);
    l.z = (unsigned short)(__float_as_uint(v.z - hif(v.z)) >> 16);
    l.w = (unsigned short)(__float_as_uint(v.w - hif(v.w)) >> 16);
    *hi = h;
    *lo = l;
}

// NT GEMM, split-bf16 x3, pre-converted operands, 2 CTAs/SM (R11 loop, best):
// C[m,n] = sum_k A[m,k]*B[n,k]; CTA tile 128x128, BK=32, 2-stage cp.async.
// 256 threads, 8 warps 4(M) x 2(N); warp tile 32x64; term-major MMA order.
// R17: next-stage cp.async issued BETWEEN ks=0 and ks=1 so the producer burst
// overlaps queued tensor work instead of preceding the first ldsm.
// FUSE=1: C = relu(acc + src + tgt + bias), also emits split-bf16 act.
template <int K, int FUSE>
__global__ __launch_bounds__(256, 2)
void mma_gemm(const uint16_t* __restrict__ Ahi, const uint16_t* __restrict__ Alo,
              const uint16_t* __restrict__ Bhi, const uint16_t* __restrict__ Blo,
              const float* __restrict__ bias,
              const float* __restrict__ src, const float* __restrict__ tgt,
              float* __restrict__ C,
              uint16_t* __restrict__ actHi, uint16_t* __restrict__ actLo,
              int N)
{
    constexpr int BK = 32;
    constexpr int KB = K / BK;
    constexpr int RS = 80;                       // row stride bytes (64B data + 16 pad)
    constexpr uint32_t ARR = 128u * RS;          // 10240 B per array
    constexpr uint32_t STAGE_BYTES = 4u * ARR;   // Ahi, Alo, Bhi, Blo = 40960 B

    extern __shared__ uint8_t sw[];
    const uint32_t sbase = smem_u32(sw);

    const int tid  = threadIdx.x;
    const int wid  = tid >> 5;
    const int lane = tid & 31;
    const int gid  = lane >> 2;
    const int tig  = lane & 3;
    const int wm   = (wid & 3) * 32;       // 4 M-warps
    const int wn   = (wid >> 2) * 64;      // 2 N-warps, 64-wide warp tile
    const long long m0 = (long long)blockIdx.y * 128;
    const int n0 = blockIdx.x * 128;

    // ldmatrix lane addressing (validated R5)
    const int a_row  = ((lane >> 3) & 1) * 8 + (lane & 7);
    const int a_koff = (lane >> 4) * 16;
    const int b_row  = (lane >> 4) * 8 + (lane & 7);
    const int b_koff = ((lane >> 3) & 1) * 16;
    const uint32_t aoff = (uint32_t)((wm + a_row) * RS + a_koff);             // Ahi array
    const uint32_t boff = 2u * ARR + (uint32_t)((wn + b_row) * RS + b_koff);  // Bhi array

    float c[2][8][4];
#pragma unroll
    for (int i = 0; i < 2; i++)
#pragma unroll
        for (int j = 0; j < 8; j++)
#pragma unroll
            for (int t = 0; t < 4; t++) c[i][j][t] = 0.0f;

    // producer: 4 arrays x 128 rows x 4 chunks(16B) = 2048 chunks / 256 thr = 8 each
    auto load_stage = [&](int kb, int buf) {
        const uint32_t stg = sbase + (uint32_t)buf * STAGE_BYTES;
#pragma unroll
        for (int t = 0; t < 8; t++) {
            const int id  = tid + t * 256;
            const int arr = id >> 9;
            const int row = (id >> 2) & 127;
            const int q   = id & 3;
            const uint32_t so = (uint32_t)arr * ARR + (uint32_t)(row * RS + q * 16);
            const uint16_t* gp;
            if (arr == 0)      gp = Ahi + (m0 + row) * (long long)K;
            else if (arr == 1) gp = Alo + (m0 + row) * (long long)K;
            else if (arr == 2) gp = Bhi + (long long)(n0 + row) * K;
            else               gp = Blo + (long long)(n0 + row) * K;
            cp16(stg + so, gp + kb * BK + q * 8);
        }
        asm volatile("cp.async.commit_group;" ::: "memory");
    };

    // one ks-step of the warp tile (term-major, acc reuse distance 16)
    auto do_ks = [&](uint32_t stg, int ks) {
        const uint32_t kB = (uint32_t)ks * 32;
        uint32_t ah[2][4], al[2][4];
#pragma unroll
        for (int mi = 0; mi < 2; mi++) {
            const uint32_t a0 = stg + aoff + mi * (16 * RS) + kB;
            ldsm4(ah[mi], a0);
            ldsm4(al[mi], a0 + ARR);
        }
        uint32_t bh[4][4];
#pragma unroll
        for (int p = 0; p < 4; p++)
            ldsm4(bh[p], stg + boff + p * (16 * RS) + kB);

        // term 1: al x bh
#pragma unroll
        for (int p = 0; p < 4; p++)
#pragma unroll
            for (int mi = 0; mi < 2; mi++)
#pragma unroll
                for (int q = 0; q < 2; q++)
                    MMA_BF16(c[mi][p * 2 + q], al[mi], &bh[p][q * 2]);

        uint32_t bl[4][4];
#pragma unroll
        for (int p = 0; p < 4; p++)
            ldsm4(bl[p], stg + boff + p * (16 * RS) + kB + ARR);

        // term 2: ah x bl
#pragma unroll
        for (int p = 0; p < 4; p++)
#pragma unroll
            for (int mi = 0; mi < 2; mi++)
#pragma unroll
                for (int q = 0; q < 2; q++)
                    MMA_BF16(c[mi][p * 2 + q], ah[mi], &bl[p][q * 2]);

        // term 3: ah x bh
#pragma unroll
        for (int p = 0; p < 4; p++)
#pragma unroll
            for (int mi = 0; mi < 2; mi++)
#pragma unroll
                for (int q = 0; q < 2; q++)
                    MMA_BF16(c[mi][p * 2 + q], ah[mi], &bh[p][q * 2]);
    };

    load_stage(0, 0);

#pragma unroll 1
    for (int kb = 0; kb < KB; kb++) {
        asm volatile("cp.async.wait_group 0;" ::: "memory");
        __syncthreads();

        const uint32_t stg = sbase + (uint32_t)(kb & 1) * STAGE_BYTES;

        // ks = 0 first: tensor pipe fills immediately after the barrier.
        do_ks(stg, 0);

        // Next-stage prefetch issues while ~48 MMAs drain from the tensor queue.
        // Buffer (kb+1)&1's previous contents (kb-1) were consumed before the
        // barrier above; safe to overwrite.
        if (kb + 1 < KB) load_stage(kb + 1, (kb + 1) & 1);

        do_ks(stg, 1);
    }

    // Epilogue: rows gid / gid+8 (per mi), cols wn + nj*8 + 2*tig, nj in [0,8)
#pragma unroll
    for (int mi = 0; mi < 2; mi++) {
#pragma unroll
        for (int half = 0; half < 2; half++) {
            const long long m = m0 + wm + mi * 16 + gid + half * 8;
            const float* srow = nullptr;
            const float* trow = nullptr;
            if (FUSE) {
                const int mi32 = (int)m;
                const int bi = mi32 / (Tt * Uu);
                const int r  = mi32 % (Tt * Uu);
                const int ti = r / Uu;
                const int ui = r % Uu;
                srow = src + (long long)(bi * Tt + ti) * Dd;
                trow = tgt + (long long)(bi * Uu + ui) * Dd;
            }
            float* crow = C + m * N;
#pragma unroll
            for (int nj = 0; nj < 8; nj++) {
                const int n = n0 + wn + nj * 8 + tig * 2;
                float2 bi2 = *(const float2*)(bias + n);
                float vx = c[mi][nj][half * 2 + 0] + bi2.x;
                float vy = c[mi][nj][half * 2 + 1] + bi2.y;
                if (FUSE) {
                    float2 s2 = *(const float2*)(srow + n);
                    float2 t2 = *(const float2*)(trow + n);
                    vx = fmaxf(vx + s2.x + t2.x, 0.0f);
                    vy = fmaxf(vy + s2.y + t2.y, 0.0f);
                }
                stcs2(crow + n, vx, vy);
                if (FUSE) {
                    const long long w = (m * N + n) >> 1;   // n even
                    ((uint32_t*)actHi)[w] = pack2hi(vx, vy);
                    ((uint32_t*)actLo)[w] = pack2hi(vx - hif(vx), vy - hif(vy));
                }
            }
        }
    }
}

// Pass-through of lengths, converted to the float32 output dtype.
__global__ void lengths_kernel(const int* __restrict__ sl, const int* __restrict__ tl,
                               float* __restrict__ out_sl, float* __restrict__ out_tl)
{
    int i = threadIdx.x;
    if (i < Bb) { out_sl[i] = (float)sl[i]; out_tl[i] = (float)tl[i]; }
}

extern "C" void kernel_launch(void* const* d_in, const int* in_sizes, int n_in,
                              void* d_out, int out_size)
{
    const float* src  = (const float*)d_in[0];   // (B, T, D)
    const int*   sl   = (const int*)  d_in[1];
    const float* tgt  = (const float*)d_in[2];   // (B, U, D)
    const int*   tl   = (const int*)  d_in[3];
    const float* hptr = (const float*)d_in[4];   // (M, A)
    const float* Wb   = (const float*)d_in[5];   // (D, A)
    const float* bb   = (const float*)d_in[6];
    const float* Wo   = (const float*)d_in[7];   // (V, D)
    const float* bo   = (const float*)d_in[8];

    float* out = (float*)d_out;
    const long long OFF_SL  = Mm * Vv;
    const long long OFF_TL  = OFF_SL + Bb;
    const long long OFF_ACT = OFF_TL + Bb;
    float* out_main = out;
    float* out_act  = out + OFF_ACT;

    uint16_t *pAhi, *pAlo, *pActHi, *pActLo, *pWbhi, *pWblo, *pWohi, *pWolo;
    cudaGetSymbolAddress((void**)&pAhi,   g_Ahi);
    cudaGetSymbolAddress((void**)&pAlo,   g_Alo);
    cudaGetSymbolAddress((void**)&pActHi, g_actHi);
    cudaGetSymbolAddress((void**)&pActLo, g_actLo);
    cudaGetSymbolAddress((void**)&pWbhi,  g_Wbhi);
    cudaGetSymbolAddress((void**)&pWblo,  g_Wblo);
    cudaGetSymbolAddress((void**)&pWohi,  g_Wohi);
    cudaGetSymbolAddress((void**)&pWolo,  g_Wolo);

    // pre-split inputs (one merged launch: hptr + Wb + Wo)
    {
        const long long nA = Mm * Aa / 4;            // 8388608
        const long long nB = (long long)Dd * Aa / 4; // 32768
        const long long nC = (long long)Vv * Dd / 4; // 131072
        const long long total = nA + nB + nC;
        split_all_kernel<<<(unsigned)((total + 255) / 256), 256>>>(
            (const float4*)hptr, (ushort4*)pAhi,  (ushort4*)pAlo,  nA,
            (const float4*)Wb,   (ushort4*)pWbhi, (ushort4*)pWblo, nB,
            (const float4*)Wo,   (ushort4*)pWohi, (ushort4*)pWolo, nC);
    }

    const int SMEM = 2 * 40960;   // 81920 B: 2 stages x 4 arrays (2 CTAs/SM)
    cudaFuncSetAttribute((const void*)mma_gemm<Aa, 1>,
                         cudaFuncAttributeMaxDynamicSharedMemorySize, SMEM);
    cudaFuncSetAttribute((const void*)mma_gemm<Dd, 0>,
                         cudaFuncAttributeMaxDynamicSharedMemorySize, SMEM);

    dim3 blk(256);
    // Kernel 1: act = relu(src + tgt + hptr @ Wb^T + bb); also emits split act
    dim3 g1(Dd / 128, (unsigned)(Mm / 128));
    mma_gemm<Aa, 1><<<g1, blk, SMEM>>>(pAhi, pAlo, pWbhi, pWblo, bb, src, tgt,
                                       out_act, pActHi, pActLo, Dd);
    // Kernel 2: out = act @ Wo^T + bo
    dim3 g2(Vv / 128, (unsigned)(Mm / 128));
    mma_gemm<Dd, 0><<<g2, blk, SMEM>>>(pActHi, pActLo, pWohi, pWolo, bo,
                                       nullptr, nullptr, out_main, nullptr, nullptr, Vv);

    lengths_kernel<<<1, 32>>>(sl, tl, out + OFF_SL, out + OFF_TL);

    (void)in_sizes; (void)n_in; (void)out_size;
}